// round 1
// baseline (speedup 1.0000x reference)
#include <cuda_runtime.h>
#include <cuda_bf16.h>

#define BATCH 16
#define NPTS 4096
#define NPAIR 2048              // target pairs per batch
#define THREADS 128
#define PP 4                    // pred points per thread
#define PRED_PER_BLOCK (THREADS*PP)     // 512
#define PRED_BLOCKS (NPTS/PRED_PER_BLOCK) // 8
#define TILE_PAIRS 1024         // target pairs per smem tile (32KB)
#define NTILES (NPAIR/TILE_PAIRS) // 2

typedef unsigned long long u64;

// Scratch (no cudaMalloc allowed): packed target format per point-pair:
//   float4 a = {x0, x1, y0, y1}; float4 b = {z0, z1, n0, n1}  (n = |p|^2)
__device__ float4 g_packS[BATCH * NPAIR * 2];  // packed "shape"
__device__ float4 g_packT[BATCH * NPAIR * 2];  // packed "template"
__device__ float  g_accum;

__device__ __forceinline__ u64 fma2(u64 a, u64 b, u64 c) {
    u64 d;
    asm("fma.rn.f32x2 %0, %1, %2, %3;" : "=l"(d) : "l"(a), "l"(b), "l"(c));
    return d;
}
__device__ __forceinline__ u64 pack2(float lo, float hi) {
    u64 d;
    asm("mov.b64 %0, {%1, %2};" : "=l"(d) : "f"(lo), "f"(hi));
    return d;
}
__device__ __forceinline__ void unpack2(u64 v, float& lo, float& hi) {
    asm("mov.b64 {%0, %1}, %2;" : "=f"(lo), "=f"(hi) : "l"(v));
}

__global__ void k_zero() { g_accum = 0.0f; }

// One thread per point-pair: read 6 contiguous floats, emit 32B packed record.
__global__ void k_pack(const float* __restrict__ shape,
                       const float* __restrict__ tmpl) {
    int idx = blockIdx.x * blockDim.x + threadIdx.x;
    if (idx >= BATCH * NPAIR) return;
    const float* src = (blockIdx.y == 0) ? shape : tmpl;
    float4* dst = (blockIdx.y == 0) ? g_packS : g_packT;
    const float* p = src + (size_t)idx * 6;   // points 2*idx, 2*idx+1
    float x0 = p[0], y0 = p[1], z0 = p[2];
    float x1 = p[3], y1 = p[4], z1 = p[5];
    float n0 = x0 * x0 + y0 * y0 + z0 * z0;
    float n1 = x1 * x1 + y1 * y1 + z1 * z1;
    dst[2 * idx]     = make_float4(x0, x1, y0, y1);
    dst[2 * idx + 1] = make_float4(z0, z1, n0, n1);
}

// Main: each block = (pred chunk, batch, direction). Each thread owns PP pred
// points (scaled by -2, duplicated into f32x2 pairs) and scans all targets:
//   val = t^2 + (-2p)·t ;  min over targets ;  dist = sqrt(max(p^2 + min, 0))
__global__ void __launch_bounds__(THREADS) k_main(const float* __restrict__ shape,
                                                  const float* __restrict__ tmpl) {
    __shared__ float4 sT[TILE_PAIRS * 2];     // 32 KB
    __shared__ float warpsum[THREADS / 32];

    const int dir = blockIdx.z;
    const int b   = blockIdx.y;
    const int t   = threadIdx.x;

    const float*  pred = (dir == 0) ? shape : tmpl;
    const float4* tgt  = ((dir == 0) ? g_packT : g_packS) + (size_t)b * NPAIR * 2;

    u64 px2[PP], py2[PP], pz2[PP];
    float p2[PP], m0[PP], m1[PP];
#pragma unroll
    for (int k = 0; k < PP; k++) {
        int i = blockIdx.x * PRED_PER_BLOCK + k * THREADS + t;
        const float* pp = pred + ((size_t)b * NPTS + i) * 3;
        float x = pp[0], y = pp[1], z = pp[2];
        p2[k] = x * x + y * y + z * z;
        float sx = -2.0f * x, sy = -2.0f * y, sz = -2.0f * z;
        px2[k] = pack2(sx, sx);
        py2[k] = pack2(sy, sy);
        pz2[k] = pack2(sz, sz);
        m0[k] = 1e30f;
        m1[k] = 1e30f;
    }

    for (int tile = 0; tile < NTILES; ++tile) {
        __syncthreads();
#pragma unroll
        for (int r = 0; r < (TILE_PAIRS * 2) / THREADS; ++r)
            sT[r * THREADS + t] = tgt[tile * TILE_PAIRS * 2 + r * THREADS + t];
        __syncthreads();

        const ulonglong2* S = (const ulonglong2*)sT;
#pragma unroll 8
        for (int j = 0; j < TILE_PAIRS; ++j) {
            ulonglong2 u0 = S[2 * j];       // .x = (tx0,tx1)  .y = (ty0,ty1)
            ulonglong2 u1 = S[2 * j + 1];   // .x = (tz0,tz1)  .y = (n0, n1)
#pragma unroll
            for (int k = 0; k < PP; k++) {
                u64 d = fma2(pz2[k], u1.x, u1.y);
                d = fma2(py2[k], u0.y, d);
                d = fma2(px2[k], u0.x, d);
                float lo, hi;
                unpack2(d, lo, hi);
                m0[k] = fminf(m0[k], lo);
                m1[k] = fminf(m1[k], hi);
            }
        }
    }

    float local = 0.0f;
#pragma unroll
    for (int k = 0; k < PP; k++) {
        float m = fminf(m0[k], m1[k]) + p2[k];
        local += sqrtf(fmaxf(m, 0.0f));
    }

    // block reduce + global atomic
#pragma unroll
    for (int o = 16; o > 0; o >>= 1)
        local += __shfl_down_sync(0xFFFFFFFFu, local, o);
    if ((t & 31) == 0) warpsum[t >> 5] = local;
    __syncthreads();
    if (t == 0) {
        float s = 0.0f;
#pragma unroll
        for (int w = 0; w < THREADS / 32; w++) s += warpsum[w];
        atomicAdd(&g_accum, s);
    }
}

__global__ void k_final(float* __restrict__ out) {
    // WEIGHT * mean over batch = 0.01 * accum / 16
    out[0] = (0.01f / 16.0f) * g_accum;
}

extern "C" void kernel_launch(void* const* d_in, const int* in_sizes, int n_in,
                              void* d_out, int out_size) {
    const float* shape = (const float*)d_in[0];
    const float* tmpl  = (const float*)d_in[1];

    k_zero<<<1, 1>>>();

    dim3 gp((BATCH * NPAIR + 255) / 256, 2);
    k_pack<<<gp, 256>>>(shape, tmpl);

    dim3 gm(PRED_BLOCKS, BATCH, 2);
    k_main<<<gm, THREADS>>>(shape, tmpl);

    k_final<<<1, 1>>>((float*)d_out);
}

// round 9
// speedup vs baseline: 1.0004x; 1.0004x over previous
#include <cuda_runtime.h>
#include <cuda_bf16.h>

#define BATCH 16
#define NPTS 4096
#define NPAIR 2048              // target pairs per batch (4096 pts / 2)
#define THREADS 128
#define PP 4                    // pred points per thread
#define PRED_PER_BLOCK (THREADS*PP)       // 512
#define PRED_BLOCKS (NPTS/PRED_PER_BLOCK) // 8
#define TILE 1024               // target pairs per CTA (half of NPAIR) -> 32KB smem

typedef unsigned long long u64;

// Packed target record per point-pair (32B):
//   float4 a = {x0, x1, y0, y1}; float4 b = {z0, z1, n0, n1}  (n = |p|^2)
__device__ float4 g_packS[BATCH * NPAIR * 2];
__device__ float4 g_packT[BATCH * NPAIR * 2];
// Partial (p^2 + min over target half) per pred point per half: [dir*16+b][half][4096]
__device__ float  g_part[2 * BATCH * 2 * NPTS];

__device__ __forceinline__ u64 fma2(u64 a, u64 b, u64 c) {
    u64 d;
    asm("fma.rn.f32x2 %0, %1, %2, %3;" : "=l"(d) : "l"(a), "l"(b), "l"(c));
    return d;
}
__device__ __forceinline__ u64 pack2(float lo, float hi) {
    u64 d;
    asm("mov.b64 %0, {%1, %2};" : "=l"(d) : "f"(lo), "f"(hi));
    return d;
}
__device__ __forceinline__ void unpack2(u64 v, float& lo, float& hi) {
    asm("mov.b64 {%0, %1}, %2;" : "=f"(lo), "=f"(hi) : "l"(v));
}

// One thread per point-pair: read 6 contiguous floats, emit 32B packed record.
// Thread (0,0) also zeroes the output scalar (final kernel atomicAdds into it).
__global__ void k_pack(const float* __restrict__ shape,
                       const float* __restrict__ tmpl,
                       float* __restrict__ out) {
    int idx = blockIdx.x * blockDim.x + threadIdx.x;
    if (blockIdx.y == 0 && idx == 0) out[0] = 0.0f;
    if (idx >= BATCH * NPAIR) return;
    const float* src = (blockIdx.y == 0) ? shape : tmpl;
    float4* dst = (blockIdx.y == 0) ? g_packS : g_packT;
    const float* p = src + (size_t)idx * 6;
    float x0 = p[0], y0 = p[1], z0 = p[2];
    float x1 = p[3], y1 = p[4], z1 = p[5];
    float n0 = x0 * x0 + y0 * y0 + z0 * z0;
    float n1 = x1 * x1 + y1 * y1 + z1 * z1;
    dst[2 * idx]     = make_float4(x0, x1, y0, y1);
    dst[2 * idx + 1] = make_float4(z0, z1, n0, n1);
}

// Block = (pred_chunk x target_half, batch, dir). 1024 CTAs total.
// Each thread owns PP pred points and scans TILE target pairs from smem:
//   c = n + (-2p)·t ; min over targets ; partial = p^2 + min
__global__ void __launch_bounds__(THREADS) k_main(const float* __restrict__ shape,
                                                  const float* __restrict__ tmpl) {
    __shared__ float4 sT[TILE * 2];   // 32 KB

    const int x     = blockIdx.x;     // 0..15
    const int chunk = x >> 1;         // 0..7
    const int half  = x & 1;          // 0..1
    const int b     = blockIdx.y;
    const int dir   = blockIdx.z;
    const int t     = threadIdx.x;

    const float*  pred = (dir == 0) ? shape : tmpl;
    const float4* tgt  = ((dir == 0) ? g_packT : g_packS)
                         + ((size_t)b * NPAIR + half * TILE) * 2;

    // Load target tile (32KB) cooperatively
#pragma unroll
    for (int r = 0; r < (TILE * 2) / THREADS; ++r)
        sT[r * THREADS + t] = tgt[r * THREADS + t];

    // Pred setup
    u64 px2[PP], py2[PP], pz2[PP];
    float p2[PP], m0[PP], m1[PP];
#pragma unroll
    for (int k = 0; k < PP; k++) {
        int i = chunk * PRED_PER_BLOCK + k * THREADS + t;
        const float* pp = pred + ((size_t)b * NPTS + i) * 3;
        float px = pp[0], py = pp[1], pz = pp[2];
        p2[k] = px * px + py * py + pz * pz;
        float sx = -2.0f * px, sy = -2.0f * py, sz = -2.0f * pz;
        px2[k] = pack2(sx, sx);
        py2[k] = pack2(sy, sy);
        pz2[k] = pack2(sz, sz);
        m0[k] = 1e30f;
        m1[k] = 1e30f;
    }

    __syncthreads();

    const ulonglong2* S = (const ulonglong2*)sT;
#pragma unroll 8
    for (int j = 0; j < TILE; ++j) {
        ulonglong2 u0 = S[2 * j];       // .x = (tx0,tx1)  .y = (ty0,ty1)
        ulonglong2 u1 = S[2 * j + 1];   // .x = (tz0,tz1)  .y = (n0, n1)
#pragma unroll
        for (int k = 0; k < PP; k++) {
            u64 d = fma2(pz2[k], u1.x, u1.y);
            d = fma2(py2[k], u0.y, d);
            d = fma2(px2[k], u0.x, d);
            float lo, hi;
            unpack2(d, lo, hi);
            m0[k] = fminf(m0[k], lo);
            m1[k] = fminf(m1[k], hi);
        }
    }

    // Write partials: p^2 + min_half  (min commutes with the +p^2 shift)
    float* part = g_part + ((size_t)(dir * BATCH + b) * 2 + half) * NPTS;
#pragma unroll
    for (int k = 0; k < PP; k++) {
        int i = chunk * PRED_PER_BLOCK + k * THREADS + t;
        part[i] = fminf(m0[k], m1[k]) + p2[k];
    }
}

// Combine halves, sqrt, reduce, scale, atomicAdd into out.
__global__ void k_final(float* __restrict__ out) {
    __shared__ float warpsum[8];
    int idx = blockIdx.x * 256 + threadIdx.x;      // 0..131071
    int du = idx >> 12;                            // dir*16+b
    int i  = idx & (NPTS - 1);
    float pa = g_part[((size_t)du * 2 + 0) * NPTS + i];
    float pb = g_part[((size_t)du * 2 + 1) * NPTS + i];
    float v = sqrtf(fmaxf(fminf(pa, pb), 0.0f));

#pragma unroll
    for (int o = 16; o > 0; o >>= 1)
        v += __shfl_down_sync(0xFFFFFFFFu, v, o);
    int t = threadIdx.x;
    if ((t & 31) == 0) warpsum[t >> 5] = v;
    __syncthreads();
    if (t == 0) {
        float s = 0.0f;
#pragma unroll
        for (int w = 0; w < 8; w++) s += warpsum[w];
        atomicAdd(out, (0.01f / 16.0f) * s);       // WEIGHT * mean over batch
    }
}

extern "C" void kernel_launch(void* const* d_in, const int* in_sizes, int n_in,
                              void* d_out, int out_size) {
    const float* shape = (const float*)d_in[0];
    const float* tmpl  = (const float*)d_in[1];
    float* out = (float*)d_out;

    dim3 gp((BATCH * NPAIR + 255) / 256, 2);
    k_pack<<<gp, 256>>>(shape, tmpl, out);

    dim3 gm(PRED_BLOCKS * 2, BATCH, 2);            // 16 x 16 x 2 = 1024 CTAs
    k_main<<<gm, THREADS>>>(shape, tmpl);

    k_final<<<(2 * BATCH * NPTS) / 256, 256>>>(out);
}